// round 7
// baseline (speedup 1.0000x reference)
#include <cuda_runtime.h>
#include <cstdint>

// Problem constants (fixed by the reference):
//   B=4, S=4096, D=2048, E=8, T=B*S=16384, C=T/E*1.25=2560, EC=E*C=20480
#define D_DIM       2048
#define T_TOK       16384
#define EC_ROWS     20480
#define BUILD_BLKS  80          // EC_ROWS / 256
#define GRID_BLKS   (T_TOK / 2) // 8192 gather blocks, 2 rows each

// Per-token work descriptor for KEPT tokens only:
//   .x = source expert row, .y = float bits of the routing factor.
// Every token in this dataset is scattered XOR dropped, so non-dropped
// tokens always have a g_work entry written by the build prologue.
__device__ int2 g_work[T_TOK];

// Single-launch synchronization. Both counters are reset to 0 by the last
// finishing block, so every graph replay sees identical initial state.
__device__ int          g_build_done = 0;
__device__ unsigned int g_finished   = 0;

__global__ __launch_bounds__(256) void moe_fused_kernel(
    const float* __restrict__ expert_outputs,   // [EC, D]
    const float* __restrict__ x,                // [T, D]
    const float* __restrict__ route_prob_max,   // [T]
    const int*   __restrict__ scatter_idx,      // [EC]
    const unsigned char* __restrict__ dropped,  // [T] bool
    float* __restrict__ out)                    // [T, D]
{
    const int tid = threadIdx.x;
    const int bid = blockIdx.x;

    // ---- Prologue: first BUILD_BLKS blocks invert the scatter map. ----
    // These bids are in wave 1 (first 148*occ bids are resident), so the
    // spin below cannot deadlock.
    if (bid < BUILD_BLKS) {
        const int i = bid * 256 + tid;          // slot index, < EC_ROWS
        const int r = scatter_idx[i];
        if (r < T_TOK) {
            g_work[r] = make_int2(i, __float_as_int(route_prob_max[r]));
        }
        __threadfence();                        // publish before counting
        __syncthreads();
        if (tid == 0) atomicAdd(&g_build_done, 1);
    }

    // ---- Barrier: wait until all build blocks have published. ----
    if (tid == 0) {
        volatile int* done = &g_build_done;
        while (*done < BUILD_BLKS) { /* spin */ }
    }
    __syncthreads();
    __threadfence();                            // acquire

    // ---- Gather body (measured-best shape): 2 rows, 128 lanes/row. ----
    const int half = tid >> 7;
    const int lane = tid & 127;
    const int t    = bid * 2 + half;

    const float4* __restrict__ src4;
    float factor;
    if (dropped[t]) {
        src4   = reinterpret_cast<const float4*>(x + (size_t)t * D_DIM);
        factor = 1.0f;
    } else {
        const int2 w = g_work[t];
        src4   = reinterpret_cast<const float4*>(expert_outputs + (size_t)w.x * D_DIM);
        factor = __int_as_float(w.y);
    }

    float4* __restrict__ dst4 =
        reinterpret_cast<float4*>(out + (size_t)t * D_DIM);

    float4 v0 = __ldcs(&src4[lane]);
    float4 v1 = __ldcs(&src4[lane + 128]);
    float4 v2 = __ldcs(&src4[lane + 256]);
    float4 v3 = __ldcs(&src4[lane + 384]);

    v0.x *= factor; v0.y *= factor; v0.z *= factor; v0.w *= factor;
    v1.x *= factor; v1.y *= factor; v1.z *= factor; v1.w *= factor;
    v2.x *= factor; v2.y *= factor; v2.z *= factor; v2.w *= factor;
    v3.x *= factor; v3.y *= factor; v3.z *= factor; v3.w *= factor;

    __stcs(&dst4[lane],       v0);
    __stcs(&dst4[lane + 128], v1);
    __stcs(&dst4[lane + 256], v2);
    __stcs(&dst4[lane + 384], v3);

    // ---- Epilogue: last block to finish resets counters for next replay. ----
    __syncthreads();
    if (tid == 0) {
        __threadfence();
        unsigned int old = atomicAdd(&g_finished, 1u);
        if (old == (unsigned int)(gridDim.x - 1)) {
            g_build_done = 0;
            atomicExch(&g_finished, 0u);
        }
    }
}

extern "C" void kernel_launch(void* const* d_in, const int* in_sizes, int n_in,
                              void* d_out, int out_size) {
    const float*         expert_outputs = (const float*)d_in[0];
    const float*         x              = (const float*)d_in[1];
    const float*         route_prob_max = (const float*)d_in[2];
    const int*           scatter_idx    = (const int*)d_in[3];
    const unsigned char* dropped        = (const unsigned char*)d_in[4];
    float* out = (float*)d_out;

    moe_fused_kernel<<<GRID_BLKS, 256>>>(
        expert_outputs, x, route_prob_max, scatter_idx, dropped, out);
}

// round 8
// speedup vs baseline: 1.1173x; 1.1173x over previous
#include <cuda_runtime.h>
#include <cstdint>

// Problem constants (fixed by the reference):
//   B=4, S=4096, D=2048, E=8, T=B*S=16384, C=T/E*1.25=2560, EC=E*C=20480
#define D_DIM   2048
#define T_TOK   16384
#define EC_ROWS 20480

// Per-token source expert row for KEPT tokens (only entry reads are for
// non-dropped tokens, all of which build_work_kernel writes each replay).
// Routing factor is read directly in the gather (indexed by t), so build is
// a pure load->store with no dependent second hop.
__device__ int g_src[T_TOK];

__global__ __launch_bounds__(256) void build_work_kernel(
    const int* __restrict__ scatter_idx)        // [EC]
{
    // Fire PDL trigger immediately: dependent gather grid may begin its
    // pre-sync work; its cudaGridDependencySynchronize() still waits for
    // our completion.
    cudaTriggerProgrammaticLaunchCompletion();

    const int i = blockIdx.x * 256 + threadIdx.x;
    if (i < EC_ROWS) {
        const int r = scatter_idx[i];
        if (r < T_TOK) g_src[r] = i;
    }
}

// Gather kernel (measured-best shape): 2 output token rows per block,
// 128 lanes per row, 4 float4 (64 B) per thread. Fully coalesced,
// sequential output writes, streaming hints (no reuse).
__global__ __launch_bounds__(256) void moe_gather_kernel(
    const float* __restrict__ expert_outputs,   // [EC, D]
    const float* __restrict__ x,                // [T, D]
    const float* __restrict__ route_prob_max,   // [T]
    const unsigned char* __restrict__ dropped,  // [T] bool
    float* __restrict__ out)                    // [T, D]
{
    const int tid  = threadIdx.x;
    const int half = tid >> 7;                  // 0 or 1: which row of the pair
    const int lane = tid & 127;
    const int t    = blockIdx.x * 2 + half;

    // Inputs not produced by build: safe to read pre-sync.
    const bool  is_dropped = dropped[t] != 0;
    const float rpm        = route_prob_max[t];

    float4* __restrict__ dst4 =
        reinterpret_cast<float4*>(out + (size_t)t * D_DIM);

    // Wait for build_work_kernel's g_src to be visible.
    cudaGridDependencySynchronize();

    const float4* __restrict__ src4;
    float factor;
    if (is_dropped) {
        src4   = reinterpret_cast<const float4*>(x + (size_t)t * D_DIM);
        factor = 1.0f;
    } else {
        const int src = g_src[t];
        src4   = reinterpret_cast<const float4*>(expert_outputs + (size_t)src * D_DIM);
        factor = rpm;
    }

    float4 v0 = __ldcs(&src4[lane]);
    float4 v1 = __ldcs(&src4[lane + 128]);
    float4 v2 = __ldcs(&src4[lane + 256]);
    float4 v3 = __ldcs(&src4[lane + 384]);

    v0.x *= factor; v0.y *= factor; v0.z *= factor; v0.w *= factor;
    v1.x *= factor; v1.y *= factor; v1.z *= factor; v1.w *= factor;
    v2.x *= factor; v2.y *= factor; v2.z *= factor; v2.w *= factor;
    v3.x *= factor; v3.y *= factor; v3.z *= factor; v3.w *= factor;

    __stcs(&dst4[lane],       v0);
    __stcs(&dst4[lane + 128], v1);
    __stcs(&dst4[lane + 256], v2);
    __stcs(&dst4[lane + 384], v3);
}

extern "C" void kernel_launch(void* const* d_in, const int* in_sizes, int n_in,
                              void* d_out, int out_size) {
    const float*         expert_outputs = (const float*)d_in[0];
    const float*         x              = (const float*)d_in[1];
    const float*         route_prob_max = (const float*)d_in[2];
    const int*           scatter_idx    = (const int*)d_in[3];
    const unsigned char* dropped        = (const unsigned char*)d_in[4];
    float* out = (float*)d_out;

    build_work_kernel<<<EC_ROWS / 256, 256>>>(scatter_idx);

    // Gather with programmatic dependent launch: overlaps build's launch ramp.
    cudaLaunchConfig_t cfg = {};
    cfg.gridDim  = dim3(T_TOK / 2, 1, 1);
    cfg.blockDim = dim3(256, 1, 1);
    cfg.dynamicSmemBytes = 0;
    cfg.stream = 0;
    cudaLaunchAttribute attrs[1];
    attrs[0].id = cudaLaunchAttributeProgrammaticStreamSerialization;
    attrs[0].val.programmaticStreamSerializationAllowed = 1;
    cfg.attrs = attrs;
    cfg.numAttrs = 1;
    cudaLaunchKernelEx(&cfg, moe_gather_kernel,
                       expert_outputs, x, route_prob_max, dropped, out);
}